// round 1
// baseline (speedup 1.0000x reference)
#include <cuda_runtime.h>
#include <cuda_bf16.h>
#include <mma.h>
#include <math.h>

using namespace nvcuda;

#define T_TOK 2048
#define HD    2048
#define ID    768
#define NE    64
#define TOPK  8
#define CAPE  512

// ---------------- scratch (device globals, no allocations) ----------------
__device__ int   g_sel [T_TOK*TOPK];
__device__ float g_wsel[T_TOK*TOPK];
__device__ int   g_slot[T_TOK*TOPK];
__device__ int   g_tok [NE*CAPE];
__device__ int   g_cnt [NE];
__device__ float g_logits[T_TOK*NE];
__device__ float g_h  [(size_t)NE*CAPE*ID];   // 100.7 MB
__device__ float g_out[(size_t)NE*CAPE*HD];   // 268 MB

// ---------------- gate logits: [2048,64] = x @ gate_w^T ----------------
__global__ __launch_bounds__(256) void gate_kernel(const float* __restrict__ x,
                                                   const float* __restrict__ gw) {
    const int t0  = blockIdx.x * 32;
    const int tid = threadIdx.x;
    __shared__ float sx[32][33];
    __shared__ float sw[32][65];
    float acc[8];
    #pragma unroll
    for (int i = 0; i < 8; i++) acc[i] = 0.f;
    const int e  = tid & 63;
    const int tb = tid >> 6;   // 0..3
    for (int k0 = 0; k0 < HD; k0 += 32) {
        #pragma unroll
        for (int j = 0; j < 4; j++) {
            int item = tid + j*256;
            int r = item >> 5, c = item & 31;
            sx[r][c] = x[(size_t)(t0 + r)*HD + k0 + c];
        }
        #pragma unroll
        for (int j = 0; j < 8; j++) {
            int item = tid + j*256;
            int ee = item >> 5, hh = item & 31;
            sw[hh][ee] = gw[(size_t)ee*HD + k0 + hh];
        }
        __syncthreads();
        #pragma unroll
        for (int hh = 0; hh < 32; hh++) {
            float wv = sw[hh][e];
            #pragma unroll
            for (int i = 0; i < 8; i++)
                acc[i] += sx[tb*8 + i][hh] * wv;
        }
        __syncthreads();
    }
    #pragma unroll
    for (int i = 0; i < 8; i++)
        g_logits[(size_t)(t0 + tb*8 + i)*NE + e] = acc[i];
}

// ---------------- softmax + top-8 + weight normalization ----------------
__global__ void topk_kernel() {
    const int t = blockIdx.x, tid = threadIdx.x; // 64 threads
    __shared__ float sp[64];
    sp[tid] = g_logits[(size_t)t*NE + tid];
    __syncthreads();
    if (tid == 0) {
        float mx = sp[0];
        for (int i = 1; i < 64; i++) mx = fmaxf(mx, sp[i]);
        for (int i = 0; i < 64; i++) sp[i] = expf(sp[i] - mx);
        // top-8 (softmax denominator cancels in the w/sum(w) renormalization)
        int idx8[8]; float w8[8]; float s8 = 0.f;
        for (int r = 0; r < 8; r++) {
            float best = -1.f; int bi = 0;
            for (int i = 0; i < 64; i++)
                if (sp[i] > best) { best = sp[i]; bi = i; }   // ties -> smallest idx
            idx8[r] = bi; w8[r] = best; s8 += best; sp[bi] = -1.f;
        }
        float inv = 1.f / s8;
        for (int r = 0; r < 8; r++) {
            g_sel [t*TOPK + r] = idx8[r];
            g_wsel[t*TOPK + r] = w8[r] * inv;
        }
    }
}

// ---------------- exact order-dependent routing (prefix counts) ----------------
__global__ void route_kernel() {
    const int e = blockIdx.x;       // one block per expert
    const int tid = threadIdx.x;    // 256 threads
    for (int s = tid; s < CAPE; s += 256) g_tok[e*CAPE + s] = -1;
    __shared__ int wsum[8];
    __shared__ int sbase;
    if (tid == 0) sbase = 0;
    __syncthreads();
    const int lane = tid & 31, wid = tid >> 5;
    for (int c = 0; c < T_TOK*TOPK; c += 256) {
        int i = c + tid;
        int ei = g_sel[i];
        bool flag = (ei == e);
        unsigned mask = __ballot_sync(0xffffffffu, flag);
        int wpre = __popc(mask & ((1u << lane) - 1u));
        if (lane == 0) wsum[wid] = __popc(mask);
        __syncthreads();
        int off = 0;
        for (int w = 0; w < wid; w++) off += wsum[w];
        int total = 0;
        for (int w = 0; w < 8; w++) total += wsum[w];
        int pos = sbase + off + wpre;
        if (flag) {
            if (pos < CAPE) {
                g_slot[i] = pos;
                g_tok[e*CAPE + pos] = i / TOPK;
            } else {
                g_slot[i] = -1;
            }
        }
        __syncthreads();
        if (tid == 0) sbase += total;
        __syncthreads();
    }
    if (tid == 0) g_cnt[e] = min(sbase, CAPE);
}

// ---------------- fused gate/up GEMM + silu epilogue ----------------
// per expert: h[512,768] = silu(A@Wg) * (A@Wu), A gathered from x, K=2048
__global__ __launch_bounds__(256, 1) void gemm1_kernel(const float* __restrict__ x,
                                                       const float* __restrict__ wgp,
                                                       const float* __restrict__ wup) {
    const int e  = blockIdx.z;
    const int m0 = blockIdx.y * 128;
    const int n0 = blockIdx.x * 64;
    if (m0 >= g_cnt[e]) return;

    __shared__ __nv_bfloat16 sAh[128*40], sAl[128*40];
    __shared__ __nv_bfloat16 sGh[32*72],  sGl[32*72];
    __shared__ __nv_bfloat16 sUh[32*72],  sUl[32*72];
    __shared__ int sTok[128];

    const int tid = threadIdx.x;
    if (tid < 128) sTok[tid] = g_tok[e*CAPE + m0 + tid];
    __syncthreads();

    const int wid = tid >> 5;
    const int wm  = wid >> 1;   // 0..3
    const int wn  = wid & 1;    // 0..1

    wmma::fragment<wmma::accumulator,16,16,16,float> cg[2][2], cu[2][2];
    #pragma unroll
    for (int i = 0; i < 2; i++)
        #pragma unroll
        for (int j = 0; j < 2; j++) { wmma::fill_fragment(cg[i][j], 0.f); wmma::fill_fragment(cu[i][j], 0.f); }

    float4 rA[4], rG[2], rU[2];

    auto load_tile = [&](int k0) {
        #pragma unroll
        for (int j = 0; j < 4; j++) {
            int item = tid + j*256;
            int r = item >> 3, c = item & 7;
            int tk = sTok[r];
            rA[j] = (tk >= 0) ? *(const float4*)(x + (size_t)tk*HD + k0 + c*4)
                              : make_float4(0.f, 0.f, 0.f, 0.f);
        }
        #pragma unroll
        for (int j = 0; j < 2; j++) {
            int item = tid + j*256;
            int r = item >> 4, c = item & 15;
            size_t off = ((size_t)e*HD + k0 + r)*ID + n0 + c*4;
            rG[j] = *(const float4*)(wgp + off);
            rU[j] = *(const float4*)(wup + off);
        }
    };
    auto split4 = [&](float4 v, __nv_bfloat16* hi, __nv_bfloat16* lo, int base) {
        float f[4] = {v.x, v.y, v.z, v.w};
        #pragma unroll
        for (int q = 0; q < 4; q++) {
            __nv_bfloat16 h = __float2bfloat16(f[q]);
            hi[base + q] = h;
            lo[base + q] = __float2bfloat16(f[q] - __bfloat162float(h));
        }
    };
    auto store_tile = [&]() {
        #pragma unroll
        for (int j = 0; j < 4; j++) {
            int item = tid + j*256;
            int r = item >> 3, c = item & 7;
            split4(rA[j], sAh, sAl, r*40 + c*4);
        }
        #pragma unroll
        for (int j = 0; j < 2; j++) {
            int item = tid + j*256;
            int r = item >> 4, c = item & 15;
            split4(rG[j], sGh, sGl, r*72 + c*4);
            split4(rU[j], sUh, sUl, r*72 + c*4);
        }
    };

    load_tile(0);
    for (int it = 0; it < HD/32; it++) {
        __syncthreads();
        store_tile();
        __syncthreads();
        if (it + 1 < HD/32) load_tile((it + 1)*32);
        #pragma unroll
        for (int kk = 0; kk < 2; kk++) {
            wmma::fragment<wmma::matrix_a,16,16,16,__nv_bfloat16,wmma::row_major> ah[2], al[2];
            wmma::fragment<wmma::matrix_b,16,16,16,__nv_bfloat16,wmma::row_major> bgh[2], bgl[2], buh[2], bul[2];
            #pragma unroll
            for (int i = 0; i < 2; i++) {
                int ao = (wm*32 + i*16)*40 + kk*16;
                wmma::load_matrix_sync(ah[i], sAh + ao, 40);
                wmma::load_matrix_sync(al[i], sAl + ao, 40);
            }
            #pragma unroll
            for (int j = 0; j < 2; j++) {
                int bo = (kk*16)*72 + wn*32 + j*16;
                wmma::load_matrix_sync(bgh[j], sGh + bo, 72);
                wmma::load_matrix_sync(bgl[j], sGl + bo, 72);
                wmma::load_matrix_sync(buh[j], sUh + bo, 72);
                wmma::load_matrix_sync(bul[j], sUl + bo, 72);
            }
            #pragma unroll
            for (int i = 0; i < 2; i++)
                #pragma unroll
                for (int j = 0; j < 2; j++) {
                    wmma::mma_sync(cg[i][j], ah[i], bgh[j], cg[i][j]);
                    wmma::mma_sync(cg[i][j], al[i], bgh[j], cg[i][j]);
                    wmma::mma_sync(cg[i][j], ah[i], bgl[j], cg[i][j]);
                    wmma::mma_sync(cu[i][j], ah[i], buh[j], cu[i][j]);
                    wmma::mma_sync(cu[i][j], al[i], buh[j], cu[i][j]);
                    wmma::mma_sync(cu[i][j], ah[i], bul[j], cu[i][j]);
                }
        }
    }
    // epilogue: h = silu(g) * u  (fragments are layout-identical -> elementwise ok)
    #pragma unroll
    for (int i = 0; i < 2; i++)
        #pragma unroll
        for (int j = 0; j < 2; j++) {
            #pragma unroll
            for (int el = 0; el < cg[i][j].num_elements; el++) {
                float g = cg[i][j].x[el];
                float u = cu[i][j].x[el];
                cg[i][j].x[el] = (g / (1.f + expf(-g))) * u;
            }
            float* hp = g_h + ((size_t)e*CAPE + m0 + wm*32 + i*16)*ID + n0 + wn*32 + j*16;
            wmma::store_matrix_sync(hp, cg[i][j], ID, wmma::mem_row_major);
        }
}

// ---------------- down GEMM: out[512,2048] = h @ wd, K=768 ----------------
__global__ __launch_bounds__(256, 1) void gemm2_kernel(const float* __restrict__ wdp) {
    const int e  = blockIdx.z;
    const int m0 = blockIdx.y * 128;
    const int n0 = blockIdx.x * 64;
    if (m0 >= g_cnt[e]) return;

    __shared__ __nv_bfloat16 sAh[128*40], sAl[128*40];
    __shared__ __nv_bfloat16 sBh[32*72],  sBl[32*72];

    const int tid = threadIdx.x;
    const int wid = tid >> 5;
    const int wm  = wid >> 1;
    const int wn  = wid & 1;

    wmma::fragment<wmma::accumulator,16,16,16,float> cc[2][2];
    #pragma unroll
    for (int i = 0; i < 2; i++)
        #pragma unroll
        for (int j = 0; j < 2; j++) wmma::fill_fragment(cc[i][j], 0.f);

    const float* Abase = g_h + (size_t)e*CAPE*ID;
    float4 rA[4], rB[2];

    auto load_tile = [&](int k0) {
        #pragma unroll
        for (int j = 0; j < 4; j++) {
            int item = tid + j*256;
            int r = item >> 3, c = item & 7;
            rA[j] = *(const float4*)(Abase + (size_t)(m0 + r)*ID + k0 + c*4);
        }
        #pragma unroll
        for (int j = 0; j < 2; j++) {
            int item = tid + j*256;
            int r = item >> 4, c = item & 15;
            rB[j] = *(const float4*)(wdp + ((size_t)e*ID + k0 + r)*HD + n0 + c*4);
        }
    };
    auto split4 = [&](float4 v, __nv_bfloat16* hi, __nv_bfloat16* lo, int base) {
        float f[4] = {v.x, v.y, v.z, v.w};
        #pragma unroll
        for (int q = 0; q < 4; q++) {
            __nv_bfloat16 h = __float2bfloat16(f[q]);
            hi[base + q] = h;
            lo[base + q] = __float2bfloat16(f[q] - __bfloat162float(h));
        }
    };
    auto store_tile = [&]() {
        #pragma unroll
        for (int j = 0; j < 4; j++) {
            int item = tid + j*256;
            int r = item >> 3, c = item & 7;
            split4(rA[j], sAh, sAl, r*40 + c*4);
        }
        #pragma unroll
        for (int j = 0; j < 2; j++) {
            int item = tid + j*256;
            int r = item >> 4, c = item & 15;
            split4(rB[j], sBh, sBl, r*72 + c*4);
        }
    };

    load_tile(0);
    for (int it = 0; it < ID/32; it++) {
        __syncthreads();
        store_tile();
        __syncthreads();
        if (it + 1 < ID/32) load_tile((it + 1)*32);
        #pragma unroll
        for (int kk = 0; kk < 2; kk++) {
            wmma::fragment<wmma::matrix_a,16,16,16,__nv_bfloat16,wmma::row_major> ah[2], al[2];
            wmma::fragment<wmma::matrix_b,16,16,16,__nv_bfloat16,wmma::row_major> bh[2], bl[2];
            #pragma unroll
            for (int i = 0; i < 2; i++) {
                int ao = (wm*32 + i*16)*40 + kk*16;
                wmma::load_matrix_sync(ah[i], sAh + ao, 40);
                wmma::load_matrix_sync(al[i], sAl + ao, 40);
            }
            #pragma unroll
            for (int j = 0; j < 2; j++) {
                int bo = (kk*16)*72 + wn*32 + j*16;
                wmma::load_matrix_sync(bh[j], sBh + bo, 72);
                wmma::load_matrix_sync(bl[j], sBl + bo, 72);
            }
            #pragma unroll
            for (int i = 0; i < 2; i++)
                #pragma unroll
                for (int j = 0; j < 2; j++) {
                    wmma::mma_sync(cc[i][j], ah[i], bh[j], cc[i][j]);
                    wmma::mma_sync(cc[i][j], al[i], bh[j], cc[i][j]);
                    wmma::mma_sync(cc[i][j], ah[i], bl[j], cc[i][j]);
                }
        }
    }
    #pragma unroll
    for (int i = 0; i < 2; i++)
        #pragma unroll
        for (int j = 0; j < 2; j++) {
            float* op = g_out + ((size_t)e*CAPE + m0 + wm*32 + i*16)*HD + n0 + wn*32 + j*16;
            wmma::store_matrix_sync(op, cc[i][j], HD, wmma::mem_row_major);
        }
}

// ---------------- deterministic gather-combine ----------------
__global__ void combine_kernel(float* __restrict__ y) {
    const int t = blockIdx.x, tid = threadIdx.x;
    __shared__ int   se[TOPK];
    __shared__ int   ss[TOPK];
    __shared__ float sw8[TOPK];
    if (tid < TOPK) {
        se[tid]  = g_sel [t*TOPK + tid];
        ss[tid]  = g_slot[t*TOPK + tid];
        sw8[tid] = g_wsel[t*TOPK + tid];
    }
    __syncthreads();
    const int c0 = tid * 8;
    float4 a0 = make_float4(0.f, 0.f, 0.f, 0.f);
    float4 a1 = a0;
    #pragma unroll
    for (int k = 0; k < TOPK; k++) {
        int sl = ss[k];
        if (sl < 0) continue;
        const float4* p = (const float4*)(g_out + ((size_t)se[k]*CAPE + sl)*HD + c0);
        float w = sw8[k];
        float4 v0 = p[0], v1 = p[1];
        a0.x = fmaf(w, v0.x, a0.x); a0.y = fmaf(w, v0.y, a0.y);
        a0.z = fmaf(w, v0.z, a0.z); a0.w = fmaf(w, v0.w, a0.w);
        a1.x = fmaf(w, v1.x, a1.x); a1.y = fmaf(w, v1.y, a1.y);
        a1.z = fmaf(w, v1.z, a1.z); a1.w = fmaf(w, v1.w, a1.w);
    }
    float4* yp = (float4*)(y + (size_t)t*HD + c0);
    yp[0] = a0;
    yp[1] = a1;
}

// ---------------- launch ----------------
extern "C" void kernel_launch(void* const* d_in, const int* in_sizes, int n_in,
                              void* d_out, int out_size) {
    const float* x      = (const float*)d_in[0];  // [1,2048,2048]
    const float* gate_w = (const float*)d_in[1];  // [64,2048]
    const float* wg     = (const float*)d_in[2];  // [64,2048,768]
    const float* wu     = (const float*)d_in[3];  // [64,2048,768]
    const float* wd     = (const float*)d_in[4];  // [64,768,2048]
    float* y = (float*)d_out;                     // [1,2048,2048]

    gate_kernel<<<T_TOK/32, 256>>>(x, gate_w);
    topk_kernel<<<T_TOK, 64>>>();
    route_kernel<<<NE, 256>>>();
    gemm1_kernel<<<dim3(ID/64, CAPE/128, NE), 256>>>(x, wg, wu);
    gemm2_kernel<<<dim3(HD/64, CAPE/128, NE), 256>>>(wd);
    combine_kernel<<<T_TOK, 256>>>(y);
}

// round 2
// speedup vs baseline: 1.0052x; 1.0052x over previous
#include <cuda_runtime.h>
#include <cuda_bf16.h>
#include <mma.h>
#include <math.h>

using namespace nvcuda;

#define T_TOK 2048
#define HD    2048
#define ID    768
#define NE    64
#define TOPK  8
#define CAPE  512

// ---------------- scratch (device globals, no allocations) ----------------
__device__ int   g_sel [T_TOK*TOPK];
__device__ float g_wsel[T_TOK*TOPK];
__device__ int   g_slot[T_TOK*TOPK];
__device__ int   g_tok [NE*CAPE];
__device__ int   g_cnt [NE];
__device__ float g_logits[T_TOK*NE];
__device__ float g_h  [(size_t)NE*CAPE*ID];   // 100.7 MB
__device__ float g_out[(size_t)NE*CAPE*HD];   // 268 MB

// ---------------- gate logits: [2048,64] = x @ gate_w^T ----------------
__global__ __launch_bounds__(256) void gate_kernel(const float* __restrict__ x,
                                                   const float* __restrict__ gw) {
    const int t0  = blockIdx.x * 32;
    const int tid = threadIdx.x;
    __shared__ float sx[32][33];
    __shared__ float sw[32][65];
    float acc[8];
    #pragma unroll
    for (int i = 0; i < 8; i++) acc[i] = 0.f;
    const int e  = tid & 63;
    const int tb = tid >> 6;   // 0..3
    for (int k0 = 0; k0 < HD; k0 += 32) {
        #pragma unroll
        for (int j = 0; j < 4; j++) {
            int item = tid + j*256;
            int r = item >> 5, c = item & 31;
            sx[r][c] = x[(size_t)(t0 + r)*HD + k0 + c];
        }
        #pragma unroll
        for (int j = 0; j < 8; j++) {
            int item = tid + j*256;
            int ee = item >> 5, hh = item & 31;
            sw[hh][ee] = gw[(size_t)ee*HD + k0 + hh];
        }
        __syncthreads();
        #pragma unroll
        for (int hh = 0; hh < 32; hh++) {
            float wv = sw[hh][e];
            #pragma unroll
            for (int i = 0; i < 8; i++)
                acc[i] += sx[tb*8 + i][hh] * wv;
        }
        __syncthreads();
    }
    #pragma unroll
    for (int i = 0; i < 8; i++)
        g_logits[(size_t)(t0 + tb*8 + i)*NE + e] = acc[i];
}

// ---------------- softmax + top-8 + weight normalization ----------------
__global__ void topk_kernel() {
    const int t = blockIdx.x, tid = threadIdx.x; // 64 threads
    __shared__ float sp[64];
    sp[tid] = g_logits[(size_t)t*NE + tid];
    __syncthreads();
    if (tid == 0) {
        float mx = sp[0];
        for (int i = 1; i < 64; i++) mx = fmaxf(mx, sp[i]);
        for (int i = 0; i < 64; i++) sp[i] = expf(sp[i] - mx);
        // top-8 (softmax denominator cancels in the w/sum(w) renormalization)
        int idx8[8]; float w8[8]; float s8 = 0.f;
        for (int r = 0; r < 8; r++) {
            float best = -1.f; int bi = 0;
            for (int i = 0; i < 64; i++)
                if (sp[i] > best) { best = sp[i]; bi = i; }   // ties -> smallest idx
            idx8[r] = bi; w8[r] = best; s8 += best; sp[bi] = -1.f;
        }
        float inv = 1.f / s8;
        for (int r = 0; r < 8; r++) {
            g_sel [t*TOPK + r] = idx8[r];
            g_wsel[t*TOPK + r] = w8[r] * inv;
        }
    }
}

// ---------------- exact order-dependent routing (prefix counts) ----------------
__global__ void route_kernel() {
    const int e = blockIdx.x;       // one block per expert
    const int tid = threadIdx.x;    // 256 threads
    for (int s = tid; s < CAPE; s += 256) g_tok[e*CAPE + s] = -1;
    __shared__ int wsum[8];
    __shared__ int sbase;
    if (tid == 0) sbase = 0;
    __syncthreads();
    const int lane = tid & 31, wid = tid >> 5;
    for (int c = 0; c < T_TOK*TOPK; c += 256) {
        int i = c + tid;
        int ei = g_sel[i];
        bool flag = (ei == e);
        unsigned mask = __ballot_sync(0xffffffffu, flag);
        int wpre = __popc(mask & ((1u << lane) - 1u));
        if (lane == 0) wsum[wid] = __popc(mask);
        __syncthreads();
        int off = 0;
        for (int w = 0; w < wid; w++) off += wsum[w];
        int total = 0;
        for (int w = 0; w < 8; w++) total += wsum[w];
        int pos = sbase + off + wpre;
        if (flag) {
            if (pos < CAPE) {
                g_slot[i] = pos;
                g_tok[e*CAPE + pos] = i / TOPK;
            } else {
                g_slot[i] = -1;
            }
        }
        __syncthreads();
        if (tid == 0) sbase += total;
        __syncthreads();
    }
    if (tid == 0) g_cnt[e] = min(sbase, CAPE);
}

// ---------------- fused gate/up GEMM + silu epilogue ----------------
// per expert: h[512,768] = silu(A@Wg) * (A@Wu), A gathered from x, K=2048
__global__ __launch_bounds__(256, 1) void gemm1_kernel(const float* __restrict__ x,
                                                       const float* __restrict__ wgp,
                                                       const float* __restrict__ wup) {
    const int e  = blockIdx.z;
    const int m0 = blockIdx.y * 128;
    const int n0 = blockIdx.x * 64;
    if (m0 >= g_cnt[e]) return;

    __shared__ __nv_bfloat16 sAh[128*40], sAl[128*40];
    __shared__ __nv_bfloat16 sGh[32*72],  sGl[32*72];
    __shared__ __nv_bfloat16 sUh[32*72],  sUl[32*72];
    __shared__ int sTok[128];

    const int tid = threadIdx.x;
    if (tid < 128) sTok[tid] = g_tok[e*CAPE + m0 + tid];
    __syncthreads();

    const int wid = tid >> 5;
    const int wm  = wid >> 1;   // 0..3
    const int wn  = wid & 1;    // 0..1

    wmma::fragment<wmma::accumulator,16,16,16,float> cg[2][2], cu[2][2];
    #pragma unroll
    for (int i = 0; i < 2; i++)
        #pragma unroll
        for (int j = 0; j < 2; j++) { wmma::fill_fragment(cg[i][j], 0.f); wmma::fill_fragment(cu[i][j], 0.f); }

    float4 rA[4], rG[2], rU[2];

    auto load_tile = [&](int k0) {
        #pragma unroll
        for (int j = 0; j < 4; j++) {
            int item = tid + j*256;
            int r = item >> 3, c = item & 7;
            int tk = sTok[r];
            rA[j] = (tk >= 0) ? *(const float4*)(x + (size_t)tk*HD + k0 + c*4)
                              : make_float4(0.f, 0.f, 0.f, 0.f);
        }
        #pragma unroll
        for (int j = 0; j < 2; j++) {
            int item = tid + j*256;
            int r = item >> 4, c = item & 15;
            size_t off = ((size_t)e*HD + k0 + r)*ID + n0 + c*4;
            rG[j] = *(const float4*)(wgp + off);
            rU[j] = *(const float4*)(wup + off);
        }
    };
    auto split4 = [&](float4 v, __nv_bfloat16* hi, __nv_bfloat16* lo, int base) {
        float f[4] = {v.x, v.y, v.z, v.w};
        #pragma unroll
        for (int q = 0; q < 4; q++) {
            __nv_bfloat16 h = __float2bfloat16(f[q]);
            hi[base + q] = h;
            lo[base + q] = __float2bfloat16(f[q] - __bfloat162float(h));
        }
    };
    auto store_tile = [&]() {
        #pragma unroll
        for (int j = 0; j < 4; j++) {
            int item = tid + j*256;
            int r = item >> 3, c = item & 7;
            split4(rA[j], sAh, sAl, r*40 + c*4);
        }
        #pragma unroll
        for (int j = 0; j < 2; j++) {
            int item = tid + j*256;
            int r = item >> 4, c = item & 15;
            split4(rG[j], sGh, sGl, r*72 + c*4);
            split4(rU[j], sUh, sUl, r*72 + c*4);
        }
    };

    load_tile(0);
    for (int it = 0; it < HD/32; it++) {
        __syncthreads();
        store_tile();
        __syncthreads();
        if (it + 1 < HD/32) load_tile((it + 1)*32);
        #pragma unroll
        for (int kk = 0; kk < 2; kk++) {
            wmma::fragment<wmma::matrix_a,16,16,16,__nv_bfloat16,wmma::row_major> ah[2], al[2];
            wmma::fragment<wmma::matrix_b,16,16,16,__nv_bfloat16,wmma::row_major> bgh[2], bgl[2], buh[2], bul[2];
            #pragma unroll
            for (int i = 0; i < 2; i++) {
                int ao = (wm*32 + i*16)*40 + kk*16;
                wmma::load_matrix_sync(ah[i], sAh + ao, 40);
                wmma::load_matrix_sync(al[i], sAl + ao, 40);
            }
            #pragma unroll
            for (int j = 0; j < 2; j++) {
                int bo = (kk*16)*72 + wn*32 + j*16;
                wmma::load_matrix_sync(bgh[j], sGh + bo, 72);
                wmma::load_matrix_sync(bgl[j], sGl + bo, 72);
                wmma::load_matrix_sync(buh[j], sUh + bo, 72);
                wmma::load_matrix_sync(bul[j], sUl + bo, 72);
            }
            #pragma unroll
            for (int i = 0; i < 2; i++)
                #pragma unroll
                for (int j = 0; j < 2; j++) {
                    wmma::mma_sync(cg[i][j], ah[i], bgh[j], cg[i][j]);
                    wmma::mma_sync(cg[i][j], al[i], bgh[j], cg[i][j]);
                    wmma::mma_sync(cg[i][j], ah[i], bgl[j], cg[i][j]);
                    wmma::mma_sync(cu[i][j], ah[i], buh[j], cu[i][j]);
                    wmma::mma_sync(cu[i][j], al[i], buh[j], cu[i][j]);
                    wmma::mma_sync(cu[i][j], ah[i], bul[j], cu[i][j]);
                }
        }
    }
    // epilogue: h = silu(g) * u  (fragments are layout-identical -> elementwise ok)
    #pragma unroll
    for (int i = 0; i < 2; i++)
        #pragma unroll
        for (int j = 0; j < 2; j++) {
            #pragma unroll
            for (int el = 0; el < cg[i][j].num_elements; el++) {
                float g = cg[i][j].x[el];
                float u = cu[i][j].x[el];
                cg[i][j].x[el] = (g / (1.f + expf(-g))) * u;
            }
            float* hp = g_h + ((size_t)e*CAPE + m0 + wm*32 + i*16)*ID + n0 + wn*32 + j*16;
            wmma::store_matrix_sync(hp, cg[i][j], ID, wmma::mem_row_major);
        }
}

// ---------------- down GEMM: out[512,2048] = h @ wd, K=768 ----------------
__global__ __launch_bounds__(256, 1) void gemm2_kernel(const float* __restrict__ wdp) {
    const int e  = blockIdx.z;
    const int m0 = blockIdx.y * 128;
    const int n0 = blockIdx.x * 64;
    if (m0 >= g_cnt[e]) return;

    __shared__ __nv_bfloat16 sAh[128*40], sAl[128*40];
    __shared__ __nv_bfloat16 sBh[32*72],  sBl[32*72];

    const int tid = threadIdx.x;
    const int wid = tid >> 5;
    const int wm  = wid >> 1;
    const int wn  = wid & 1;

    wmma::fragment<wmma::accumulator,16,16,16,float> cc[2][2];
    #pragma unroll
    for (int i = 0; i < 2; i++)
        #pragma unroll
        for (int j = 0; j < 2; j++) wmma::fill_fragment(cc[i][j], 0.f);

    const float* Abase = g_h + (size_t)e*CAPE*ID;
    float4 rA[4], rB[2];

    auto load_tile = [&](int k0) {
        #pragma unroll
        for (int j = 0; j < 4; j++) {
            int item = tid + j*256;
            int r = item >> 3, c = item & 7;
            rA[j] = *(const float4*)(Abase + (size_t)(m0 + r)*ID + k0 + c*4);
        }
        #pragma unroll
        for (int j = 0; j < 2; j++) {
            int item = tid + j*256;
            int r = item >> 4, c = item & 15;
            rB[j] = *(const float4*)(wdp + ((size_t)e*ID + k0 + r)*HD + n0 + c*4);
        }
    };
    auto split4 = [&](float4 v, __nv_bfloat16* hi, __nv_bfloat16* lo, int base) {
        float f[4] = {v.x, v.y, v.z, v.w};
        #pragma unroll
        for (int q = 0; q < 4; q++) {
            __nv_bfloat16 h = __float2bfloat16(f[q]);
            hi[base + q] = h;
            lo[base + q] = __float2bfloat16(f[q] - __bfloat162float(h));
        }
    };
    auto store_tile = [&]() {
        #pragma unroll
        for (int j = 0; j < 4; j++) {
            int item = tid + j*256;
            int r = item >> 3, c = item & 7;
            split4(rA[j], sAh, sAl, r*40 + c*4);
        }
        #pragma unroll
        for (int j = 0; j < 2; j++) {
            int item = tid + j*256;
            int r = item >> 4, c = item & 15;
            split4(rB[j], sBh, sBl, r*72 + c*4);
        }
    };

    load_tile(0);
    for (int it = 0; it < ID/32; it++) {
        __syncthreads();
        store_tile();
        __syncthreads();
        if (it + 1 < ID/32) load_tile((it + 1)*32);
        #pragma unroll
        for (int kk = 0; kk < 2; kk++) {
            wmma::fragment<wmma::matrix_a,16,16,16,__nv_bfloat16,wmma::row_major> ah[2], al[2];
            wmma::fragment<wmma::matrix_b,16,16,16,__nv_bfloat16,wmma::row_major> bh[2], bl[2];
            #pragma unroll
            for (int i = 0; i < 2; i++) {
                int ao = (wm*32 + i*16)*40 + kk*16;
                wmma::load_matrix_sync(ah[i], sAh + ao, 40);
                wmma::load_matrix_sync(al[i], sAl + ao, 40);
            }
            #pragma unroll
            for (int j = 0; j < 2; j++) {
                int bo = (kk*16)*72 + wn*32 + j*16;
                wmma::load_matrix_sync(bh[j], sBh + bo, 72);
                wmma::load_matrix_sync(bl[j], sBl + bo, 72);
            }
            #pragma unroll
            for (int i = 0; i < 2; i++)
                #pragma unroll
                for (int j = 0; j < 2; j++) {
                    wmma::mma_sync(cc[i][j], ah[i], bh[j], cc[i][j]);
                    wmma::mma_sync(cc[i][j], al[i], bh[j], cc[i][j]);
                    wmma::mma_sync(cc[i][j], ah[i], bl[j], cc[i][j]);
                }
        }
    }
    #pragma unroll
    for (int i = 0; i < 2; i++)
        #pragma unroll
        for (int j = 0; j < 2; j++) {
            float* op = g_out + ((size_t)e*CAPE + m0 + wm*32 + i*16)*HD + n0 + wn*32 + j*16;
            wmma::store_matrix_sync(op, cc[i][j], HD, wmma::mem_row_major);
        }
}

// ---------------- deterministic gather-combine ----------------
__global__ void combine_kernel(float* __restrict__ y) {
    const int t = blockIdx.x, tid = threadIdx.x;
    __shared__ int   se[TOPK];
    __shared__ int   ss[TOPK];
    __shared__ float sw8[TOPK];
    if (tid < TOPK) {
        se[tid]  = g_sel [t*TOPK + tid];
        ss[tid]  = g_slot[t*TOPK + tid];
        sw8[tid] = g_wsel[t*TOPK + tid];
    }
    __syncthreads();
    const int c0 = tid * 8;
    float4 a0 = make_float4(0.f, 0.f, 0.f, 0.f);
    float4 a1 = a0;
    #pragma unroll
    for (int k = 0; k < TOPK; k++) {
        int sl = ss[k];
        if (sl < 0) continue;
        const float4* p = (const float4*)(g_out + ((size_t)se[k]*CAPE + sl)*HD + c0);
        float w = sw8[k];
        float4 v0 = p[0], v1 = p[1];
        a0.x = fmaf(w, v0.x, a0.x); a0.y = fmaf(w, v0.y, a0.y);
        a0.z = fmaf(w, v0.z, a0.z); a0.w = fmaf(w, v0.w, a0.w);
        a1.x = fmaf(w, v1.x, a1.x); a1.y = fmaf(w, v1.y, a1.y);
        a1.z = fmaf(w, v1.z, a1.z); a1.w = fmaf(w, v1.w, a1.w);
    }
    float4* yp = (float4*)(y + (size_t)t*HD + c0);
    yp[0] = a0;
    yp[1] = a1;
}

// ---------------- launch ----------------
extern "C" void kernel_launch(void* const* d_in, const int* in_sizes, int n_in,
                              void* d_out, int out_size) {
    const float* x      = (const float*)d_in[0];  // [1,2048,2048]
    const float* gate_w = (const float*)d_in[1];  // [64,2048]
    const float* wg     = (const float*)d_in[2];  // [64,2048,768]
    const float* wu     = (const float*)d_in[3];  // [64,2048,768]
    const float* wd     = (const float*)d_in[4];  // [64,768,2048]
    float* y = (float*)d_out;                     // [1,2048,2048]

    gate_kernel<<<T_TOK/32, 256>>>(x, gate_w);
    topk_kernel<<<T_TOK, 64>>>();
    route_kernel<<<NE, 256>>>();
    gemm1_kernel<<<dim3(ID/64, CAPE/128, NE), 256>>>(x, wg, wu);
    gemm2_kernel<<<dim3(HD/64, CAPE/128, NE), 256>>>(wd);
    combine_kernel<<<T_TOK, 256>>>(y);
}

// round 4
// speedup vs baseline: 1.8384x; 1.8289x over previous
#include <cuda_runtime.h>
#include <cuda_bf16.h>
#include <stdint.h>
#include <math.h>

#define T_TOK 2048
#define HD    2048
#define ID    768
#define NE    64
#define TOPK  8
#define CAPE  512

// ---------------- scratch (device globals) ----------------
__device__ int   g_sel [T_TOK*TOPK];
__device__ float g_wsel[T_TOK*TOPK];
__device__ int   g_slot[T_TOK*TOPK];
__device__ int   g_tok [NE*CAPE];
__device__ int   g_cnt [NE];
__device__ float g_logits[T_TOK*NE];
__device__ __nv_bfloat16 g_xh[(size_t)T_TOK*HD],  g_xl[(size_t)T_TOK*HD];
__device__ __nv_bfloat16 g_wgh[(size_t)NE*HD*ID], g_wgl[(size_t)NE*HD*ID];
__device__ __nv_bfloat16 g_wuh[(size_t)NE*HD*ID], g_wul[(size_t)NE*HD*ID];
__device__ __nv_bfloat16 g_wdh[(size_t)NE*ID*HD], g_wdl[(size_t)NE*ID*HD];
__device__ __nv_bfloat16 g_hh [(size_t)NE*CAPE*ID], g_hl[(size_t)NE*CAPE*ID];
__device__ float g_out[(size_t)NE*CAPE*HD];

// ---------------- helpers ----------------
__device__ __forceinline__ uint32_t s2u(const void* p) {
    uint32_t a;
    asm("{ .reg .u64 t; cvta.to.shared.u64 t, %1; cvt.u32.u64 %0, t; }" : "=r"(a) : "l"(p));
    return a;
}
__device__ __forceinline__ uint32_t sw(uint32_t off) {   // Swizzle<3,4,3> on flat bytes
    return off ^ (((off >> 7) & 7u) << 4);
}
__device__ __forceinline__ void cpa(uint32_t d, const void* s, int nb) {
    asm volatile("cp.async.cg.shared.global [%0], [%1], 16, %2;"
                 :: "r"(d), "l"(s), "r"(nb) : "memory");
}
#define CP_COMMIT() asm volatile("cp.async.commit_group;" ::: "memory")
#define CP_WAIT2()  asm volatile("cp.async.wait_group 2;" ::: "memory")

__device__ __forceinline__ void ldsm4(uint32_t& r0, uint32_t& r1, uint32_t& r2, uint32_t& r3, uint32_t a) {
    asm volatile("ldmatrix.sync.aligned.m8n8.x4.shared.b16 {%0,%1,%2,%3}, [%4];"
                 : "=r"(r0), "=r"(r1), "=r"(r2), "=r"(r3) : "r"(a));
}
__device__ __forceinline__ void ldsm4t(uint32_t& r0, uint32_t& r1, uint32_t& r2, uint32_t& r3, uint32_t a) {
    asm volatile("ldmatrix.sync.aligned.m8n8.x4.trans.shared.b16 {%0,%1,%2,%3}, [%4];"
                 : "=r"(r0), "=r"(r1), "=r"(r2), "=r"(r3) : "r"(a));
}
__device__ __forceinline__ void mma16816(float* c, const uint32_t* a, const uint32_t* b) {
    asm volatile("mma.sync.aligned.m16n8k16.row.col.f32.bf16.bf16.f32 "
                 "{%0,%1,%2,%3}, {%4,%5,%6,%7}, {%8,%9}, {%0,%1,%2,%3};"
                 : "+f"(c[0]), "+f"(c[1]), "+f"(c[2]), "+f"(c[3])
                 : "r"(a[0]), "r"(a[1]), "r"(a[2]), "r"(a[3]), "r"(b[0]), "r"(b[1]));
}

// ---------------- conversion: fp32 -> bf16 hi/lo ----------------
__global__ void convert_kernel(const float* __restrict__ src, int sel, int n4) {
    __nv_bfloat16 *hi, *lo;
    if      (sel == 0) { hi = g_xh;  lo = g_xl;  }
    else if (sel == 1) { hi = g_wgh; lo = g_wgl; }
    else if (sel == 2) { hi = g_wuh; lo = g_wul; }
    else               { hi = g_wdh; lo = g_wdl; }
    for (int i = blockIdx.x*blockDim.x + threadIdx.x; i < n4; i += gridDim.x*blockDim.x) {
        float4 v = ((const float4*)src)[i];
        __nv_bfloat162 a  = __floats2bfloat162_rn(v.x, v.y);
        __nv_bfloat162 b  = __floats2bfloat162_rn(v.z, v.w);
        __nv_bfloat162 ra = __floats2bfloat162_rn(v.x - __low2float(a), v.y - __high2float(a));
        __nv_bfloat162 rb = __floats2bfloat162_rn(v.z - __low2float(b), v.w - __high2float(b));
        ((uint2*)hi)[i] = make_uint2(*reinterpret_cast<uint32_t*>(&a),  *reinterpret_cast<uint32_t*>(&b));
        ((uint2*)lo)[i] = make_uint2(*reinterpret_cast<uint32_t*>(&ra), *reinterpret_cast<uint32_t*>(&rb));
    }
}

// ---------------- gate logits ----------------
__global__ __launch_bounds__(256) void gate_kernel(const float* __restrict__ x,
                                                   const float* __restrict__ gw) {
    const int t0  = blockIdx.x * 32;
    const int tid = threadIdx.x;
    __shared__ float sx[32][33];
    __shared__ float swt[32][65];
    float acc[8];
    #pragma unroll
    for (int i = 0; i < 8; i++) acc[i] = 0.f;
    const int e  = tid & 63;
    const int tb = tid >> 6;
    for (int k0 = 0; k0 < HD; k0 += 32) {
        #pragma unroll
        for (int j = 0; j < 4; j++) {
            int item = tid + j*256;
            int r = item >> 5, c = item & 31;
            sx[r][c] = x[(size_t)(t0 + r)*HD + k0 + c];
        }
        #pragma unroll
        for (int j = 0; j < 8; j++) {
            int item = tid + j*256;
            int ee = item >> 5, hh = item & 31;
            swt[hh][ee] = gw[(size_t)ee*HD + k0 + hh];
        }
        __syncthreads();
        #pragma unroll
        for (int hh = 0; hh < 32; hh++) {
            float wv = swt[hh][e];
            #pragma unroll
            for (int i = 0; i < 8; i++)
                acc[i] += sx[tb*8 + i][hh] * wv;
        }
        __syncthreads();
    }
    #pragma unroll
    for (int i = 0; i < 8; i++)
        g_logits[(size_t)(t0 + tb*8 + i)*NE + e] = acc[i];
}

// ---------------- top-8 ----------------
__global__ void topk_kernel() {
    const int t = blockIdx.x, tid = threadIdx.x;
    __shared__ float sp[64];
    sp[tid] = g_logits[(size_t)t*NE + tid];
    __syncthreads();
    if (tid == 0) {
        float mx = sp[0];
        for (int i = 1; i < 64; i++) mx = fmaxf(mx, sp[i]);
        for (int i = 0; i < 64; i++) sp[i] = expf(sp[i] - mx);
        int idx8[8]; float w8[8]; float s8 = 0.f;
        for (int r = 0; r < 8; r++) {
            float best = -1.f; int bi = 0;
            for (int i = 0; i < 64; i++)
                if (sp[i] > best) { best = sp[i]; bi = i; }
            idx8[r] = bi; w8[r] = best; s8 += best; sp[bi] = -1.f;
        }
        float inv = 1.f / s8;
        for (int r = 0; r < 8; r++) {
            g_sel [t*TOPK + r] = idx8[r];
            g_wsel[t*TOPK + r] = w8[r] * inv;
        }
    }
}

// ---------------- routing (exact prefix order) ----------------
__global__ void route_kernel() {
    const int e = blockIdx.x;
    const int tid = threadIdx.x;
    for (int s = tid; s < CAPE; s += 256) g_tok[e*CAPE + s] = -1;
    __shared__ int wsum[8];
    __shared__ int sbase;
    if (tid == 0) sbase = 0;
    __syncthreads();
    const int lane = tid & 31, wid = tid >> 5;
    for (int c = 0; c < T_TOK*TOPK; c += 256) {
        int i = c + tid;
        int ei = g_sel[i];
        bool flag = (ei == e);
        unsigned mask = __ballot_sync(0xffffffffu, flag);
        int wpre = __popc(mask & ((1u << lane) - 1u));
        if (lane == 0) wsum[wid] = __popc(mask);
        __syncthreads();
        int off = 0;
        for (int w = 0; w < wid; w++) off += wsum[w];
        int total = 0;
        for (int w = 0; w < 8; w++) total += wsum[w];
        int pos = sbase + off + wpre;
        if (flag) {
            if (pos < CAPE) {
                g_slot[i] = pos;
                g_tok[e*CAPE + pos] = i / TOPK;
            } else {
                g_slot[i] = -1;
            }
        }
        __syncthreads();
        if (tid == 0) sbase += total;
        __syncthreads();
    }
    if (tid == 0) g_cnt[e] = min(sbase, CAPE);
}

// ================= GEMM1: h = silu(A@Wg)*(A@Wu) =================
// CTA: M=128, N=64 (both G and U), K-chunks of 32, 4-stage cp.async pipeline.
// Stage layout (32KB): AH@0(8K) AL@8192 GH@16384(4K) GL@20480 UH@24576 UL@28672
#define STG 32768
#define G_SMEM (2048 + 4*STG)

__global__ __launch_bounds__(256, 1) void gemm1_kernel() {
    const int e  = blockIdx.z;
    const int m0 = blockIdx.y * 128;
    const int n0 = blockIdx.x * 64;
    if (m0 >= g_cnt[e]) return;

    extern __shared__ __align__(1024) char smem_raw[];
    const uint32_t su = s2u(smem_raw);
    const uint32_t tb = (su + 1024 + 1023) & ~1023u;
    int* sTok = (int*)smem_raw;

    const int tid = threadIdx.x;
    if (tid < 128) sTok[tid] = g_tok[e*CAPE + m0 + tid];
    __syncthreads();

    // staging maps
    const int mA  = tid >> 2, kcA = tid & 3;
    const uint32_t dA0 = sw((uint32_t)(mA*64      + kcA*16));
    const uint32_t dA1 = sw((uint32_t)((mA+64)*64 + kcA*16));
    const int kB = tid >> 3, ncB = tid & 7;
    const uint32_t dB = sw((uint32_t)(kB*128 + ncB*16));
    const int tk0 = sTok[mA], tk1 = sTok[mA+64];
    const int nb0 = tk0 >= 0 ? 16 : 0, nb1 = tk1 >= 0 ? 16 : 0;
    const __nv_bfloat16* ah0 = g_xh + (size_t)(tk0 >= 0 ? tk0 : 0)*HD + kcA*8;
    const __nv_bfloat16* al0 = g_xl + (size_t)(tk0 >= 0 ? tk0 : 0)*HD + kcA*8;
    const __nv_bfloat16* ah1 = g_xh + (size_t)(tk1 >= 0 ? tk1 : 0)*HD + kcA*8;
    const __nv_bfloat16* al1 = g_xl + (size_t)(tk1 >= 0 ? tk1 : 0)*HD + kcA*8;

    auto issue = [&](int it) {
        const int k0 = it * 32;
        const uint32_t sb = tb + (uint32_t)(it & 3) * STG;
        cpa(sb + dA0,        ah0 + k0, nb0);
        cpa(sb + 8192 + dA0, al0 + k0, nb0);
        cpa(sb + dA1,        ah1 + k0, nb1);
        cpa(sb + 8192 + dA1, al1 + k0, nb1);
        const size_t go = ((size_t)e*HD + k0 + kB)*ID + n0 + ncB*8;
        cpa(sb + 16384 + dB, g_wgh + go, 16);
        cpa(sb + 20480 + dB, g_wgl + go, 16);
        cpa(sb + 24576 + dB, g_wuh + go, 16);
        cpa(sb + 28672 + dB, g_wul + go, 16);
        CP_COMMIT();
    };

    const int lane = tid & 31, wid = tid >> 5;
    const int wm = wid >> 1, wn = wid & 1;
    uint32_t offA[2][2], offB[2][2];
    #pragma unroll
    for (int tm = 0; tm < 2; tm++)
        #pragma unroll
        for (int ks = 0; ks < 2; ks++)
            offA[tm][ks] = sw((uint32_t)((wm*32 + tm*16 + (lane & 15))*64 + ks*32 + (lane >> 4)*16));
    #pragma unroll
    for (int ks = 0; ks < 2; ks++)
        #pragma unroll
        for (int nh = 0; nh < 2; nh++)
            offB[ks][nh] = sw((uint32_t)((ks*16 + (lane & 15))*128 + wn*64 + nh*32 + (lane >> 4)*16));

    float cG[2][4][4], cU[2][4][4];
    #pragma unroll
    for (int a = 0; a < 2; a++)
        #pragma unroll
        for (int b = 0; b < 4; b++)
            #pragma unroll
            for (int c = 0; c < 4; c++) { cG[a][b][c] = 0.f; cU[a][b][c] = 0.f; }

    issue(0); issue(1); issue(2);

    #pragma unroll 1
    for (int it = 0; it < HD/32; it++) {
        CP_WAIT2();
        __syncthreads();
        if (it + 3 < HD/32) issue(it + 3);
        else CP_COMMIT();
        const uint32_t sb = tb + (uint32_t)(it & 3) * STG;
        #pragma unroll
        for (int ks = 0; ks < 2; ks++) {
            uint32_t aH[2][4], aL[2][4];
            #pragma unroll
            for (int tm = 0; tm < 2; tm++) {
                ldsm4(aH[tm][0], aH[tm][1], aH[tm][2], aH[tm][3], sb + offA[tm][ks]);
                ldsm4(aL[tm][0], aL[tm][1], aL[tm][2], aL[tm][3], sb + 8192 + offA[tm][ks]);
            }
            // ---- G ----
            {
                uint32_t bh[4][2], bl[4][2];
                #pragma unroll
                for (int nh = 0; nh < 2; nh++) {
                    ldsm4t(bh[nh*2][0], bh[nh*2][1], bh[nh*2+1][0], bh[nh*2+1][1], sb + 16384 + offB[ks][nh]);
                    ldsm4t(bl[nh*2][0], bl[nh*2][1], bl[nh*2+1][0], bl[nh*2+1][1], sb + 20480 + offB[ks][nh]);
                }
                #pragma unroll
                for (int tm = 0; tm < 2; tm++)
                    #pragma unroll
                    for (int tn = 0; tn < 4; tn++) {
                        mma16816(cG[tm][tn], aH[tm], bh[tn]);
                        mma16816(cG[tm][tn], aL[tm], bh[tn]);
                        mma16816(cG[tm][tn], aH[tm], bl[tn]);
                    }
            }
            // ---- U ----
            {
                uint32_t bh[4][2], bl[4][2];
                #pragma unroll
                for (int nh = 0; nh < 2; nh++) {
                    ldsm4t(bh[nh*2][0], bh[nh*2][1], bh[nh*2+1][0], bh[nh*2+1][1], sb + 24576 + offB[ks][nh]);
                    ldsm4t(bl[nh*2][0], bl[nh*2][1], bl[nh*2+1][0], bl[nh*2+1][1], sb + 28672 + offB[ks][nh]);
                }
                #pragma unroll
                for (int tm = 0; tm < 2; tm++)
                    #pragma unroll
                    for (int tn = 0; tn < 4; tn++) {
                        mma16816(cU[tm][tn], aH[tm], bh[tn]);
                        mma16816(cU[tm][tn], aL[tm], bh[tn]);
                        mma16816(cU[tm][tn], aH[tm], bl[tn]);
                    }
            }
        }
    }

    // epilogue: h = silu(G)*U -> bf16 hi/lo
    const int r4 = lane >> 2, cp2 = (lane & 3) * 2;
    #pragma unroll
    for (int tm = 0; tm < 2; tm++)
        #pragma unroll
        for (int tn = 0; tn < 4; tn++) {
            const int row0 = m0 + wm*32 + tm*16 + r4;
            const int col  = n0 + wn*32 + tn*8 + cp2;
            #pragma unroll
            for (int half = 0; half < 2; half++) {
                float g0 = cG[tm][tn][half*2],     u0 = cU[tm][tn][half*2];
                float g1 = cG[tm][tn][half*2 + 1], u1 = cU[tm][tn][half*2 + 1];
                float h0 = g0 / (1.f + __expf(-g0)) * u0;
                float h1 = g1 / (1.f + __expf(-g1)) * u1;
                __nv_bfloat162 hh = __floats2bfloat162_rn(h0, h1);
                __nv_bfloat162 ll = __floats2bfloat162_rn(h0 - __low2float(hh), h1 - __high2float(hh));
                const size_t o = ((size_t)e*CAPE + row0 + half*8)*ID + col;
                *(uint32_t*)(g_hh + o) = *reinterpret_cast<uint32_t*>(&hh);
                *(uint32_t*)(g_hl + o) = *reinterpret_cast<uint32_t*>(&ll);
            }
        }
}

// ================= GEMM2: out = h @ wd =================
// CTA: M=128, N=128 (2 slabs of 64), K-chunks of 32, 4 stages.
// Stage layout (32KB): AH@0 AL@8192 BH@16384(2 slabs x 4K) BL@24576
__global__ __launch_bounds__(256, 1) void gemm2_kernel() {
    const int e  = blockIdx.z;
    const int m0 = blockIdx.y * 128;
    const int n0 = blockIdx.x * 128;
    if (m0 >= g_cnt[e]) return;

    extern __shared__ __align__(1024) char smem_raw[];
    const uint32_t su = s2u(smem_raw);
    const uint32_t tb = (su + 1024 + 1023) & ~1023u;
    const int tid = threadIdx.x;

    // staging maps: A 2 chunks/thread/array, B 2 chunks/thread/array
    const int mA = tid >> 2, kcA = tid & 3;
    const uint32_t dA0 = sw((uint32_t)(mA*64      + kcA*16));
    const uint32_t dA1 = sw((uint32_t)((mA+64)*64 + kcA*16));
    const int kB0 = tid >> 4,        ncB0 = tid & 15;
    const int kB1 = (tid + 256) >> 4, ncB1 = ncB0;   // kB1 = kB0 + 16
    const uint32_t dB0 = (uint32_t)((ncB0 >> 3)*4096) + sw((uint32_t)(kB0*128 + (ncB0 & 7)*16));
    const uint32_t dB1 = (uint32_t)((ncB1 >> 3)*4096) + sw((uint32_t)((kB0+16)*128 + (ncB1 & 7)*16));

    auto issue = [&](int it) {
        const int k0 = it * 32;
        const uint32_t sb = tb + (uint32_t)(it & 3) * STG;
        const size_t ga0 = ((size_t)e*CAPE + m0 + mA)*ID + k0 + kcA*8;
        const size_t ga1 = ((size_t)e*CAPE + m0 + mA + 64)*ID + k0 + kcA*8;
        cpa(sb + dA0,        g_hh + ga0, 16);
        cpa(sb + 8192 + dA0, g_hl + ga0, 16);
        cpa(sb + dA1,        g_hh + ga1, 16);
        cpa(sb + 8192 + dA1, g_hl + ga1, 16);
        const size_t gb0 = ((size_t)e*ID + k0 + kB0)*HD + n0 + ncB0*8;
        const size_t gb1 = ((size_t)e*ID + k0 + kB0 + 16)*HD + n0 + ncB1*8;
        cpa(sb + 16384 + dB0, g_wdh + gb0, 16);
        cpa(sb + 24576 + dB0, g_wdl + gb0, 16);
        cpa(sb + 16384 + dB1, g_wdh + gb1, 16);
        cpa(sb + 24576 + dB1, g_wdl + gb1, 16);
        CP_COMMIT();
    };

    const int lane = tid & 31, wid = tid >> 5;
    const int wm = wid >> 1, wn = wid & 1;
    uint32_t offA[2][2], offB[2][4];
    #pragma unroll
    for (int tm = 0; tm < 2; tm++)
        #pragma unroll
        for (int ks = 0; ks < 2; ks++)
            offA[tm][ks] = sw((uint32_t)((wm*32 + tm*16 + (lane & 15))*64 + ks*32 + (lane >> 4)*16));
    #pragma unroll
    for (int ks = 0; ks < 2; ks++)
        #pragma unroll
        for (int nh = 0; nh < 4; nh++)
            offB[ks][nh] = (uint32_t)(wn*4096) +
                           sw((uint32_t)((ks*16 + (lane & 15))*128 + nh*32 + (lane >> 4)*16));

    float cc[2][8][4];
    #pragma unroll
    for (int a = 0; a < 2; a++)
        #pragma unroll
        for (int b = 0; b < 8; b++)
            #pragma unroll
            for (int c = 0; c < 4; c++) cc[a][b][c] = 0.f;

    issue(0); issue(1); issue(2);

    #pragma unroll 1
    for (int it = 0; it < ID/32; it++) {
        CP_WAIT2();
        __syncthreads();
        if (it + 3 < ID/32) issue(it + 3);
        else CP_COMMIT();
        const uint32_t sb = tb + (uint32_t)(it & 3) * STG;
        #pragma unroll
        for (int ks = 0; ks < 2; ks++) {
            uint32_t aH[2][4], aL[2][4];
            #pragma unroll
            for (int tm = 0; tm < 2; tm++) {
                ldsm4(aH[tm][0], aH[tm][1], aH[tm][2], aH[tm][3], sb + offA[tm][ks]);
                ldsm4(aL[tm][0], aL[tm][1], aL[tm][2], aL[tm][3], sb + 8192 + offA[tm][ks]);
            }
            uint32_t bh[8][2], bl[8][2];
            #pragma unroll
            for (int nh = 0; nh < 4; nh++) {
                ldsm4t(bh[nh*2][0], bh[nh*2][1], bh[nh*2+1][0], bh[nh*2+1][1], sb + 16384 + offB[ks][nh]);
                ldsm4t(bl[nh*2][0], bl[nh*2][1], bl[nh*2+1][0], bl[nh*2+1][1], sb + 24576 + offB[ks][nh]);
            }
            #pragma unroll
            for (int tm = 0; tm < 2; tm++)
                #pragma unroll
                for (int tn = 0; tn < 8; tn++) {
                    mma16816(cc[tm][tn], aH[tm], bh[tn]);
                    mma16816(cc[tm][tn], aL[tm], bh[tn]);
                    mma16816(cc[tm][tn], aH[tm], bl[tn]);
                }
        }
    }

    const int r4 = lane >> 2, cp2 = (lane & 3) * 2;
    #pragma unroll
    for (int tm = 0; tm < 2; tm++)
        #pragma unroll
        for (int tn = 0; tn < 8; tn++) {
            const int row0 = m0 + wm*32 + tm*16 + r4;
            const int col  = n0 + wn*64 + tn*8 + cp2;
            #pragma unroll
            for (int half = 0; half < 2; half++) {
                const size_t o = ((size_t)e*CAPE + row0 + half*8)*HD + col;
                *(float2*)(g_out + o) = make_float2(cc[tm][tn][half*2], cc[tm][tn][half*2 + 1]);
            }
        }
}

// ---------------- combine ----------------
__global__ void combine_kernel(float* __restrict__ y) {
    const int t = blockIdx.x, tid = threadIdx.x;
    __shared__ int   se[TOPK];
    __shared__ int   ss[TOPK];
    __shared__ float sw8[TOPK];
    if (tid < TOPK) {
        se[tid]  = g_sel [t*TOPK + tid];
        ss[tid]  = g_slot[t*TOPK + tid];
        sw8[tid] = g_wsel[t*TOPK + tid];
    }
    __syncthreads();
    const int c0 = tid * 8;
    float4 a0 = make_float4(0.f, 0.f, 0.f, 0.f);
    float4 a1 = a0;
    #pragma unroll
    for (int k = 0; k < TOPK; k++) {
        int sl = ss[k];
        if (sl < 0) continue;
        const float4* p = (const float4*)(g_out + ((size_t)se[k]*CAPE + sl)*HD + c0);
        float w = sw8[k];
        float4 v0 = p[0], v1 = p[1];
        a0.x = fmaf(w, v0.x, a0.x); a0.y = fmaf(w, v0.y, a0.y);
        a0.z = fmaf(w, v0.z, a0.z); a0.w = fmaf(w, v0.w, a0.w);
        a1.x = fmaf(w, v1.x, a1.x); a1.y = fmaf(w, v1.y, a1.y);
        a1.z = fmaf(w, v1.z, a1.z); a1.w = fmaf(w, v1.w, a1.w);
    }
    float4* yp = (float4*)(y + (size_t)t*HD + c0);
    yp[0] = a0;
    yp[1] = a1;
}

// ---------------- launch ----------------
extern "C" void kernel_launch(void* const* d_in, const int* in_sizes, int n_in,
                              void* d_out, int out_size) {
    const float* x      = (const float*)d_in[0];
    const float* gate_w = (const float*)d_in[1];
    const float* wg     = (const float*)d_in[2];
    const float* wu     = (const float*)d_in[3];
    const float* wd     = (const float*)d_in[4];
    float* y = (float*)d_out;

    cudaFuncSetAttribute(gemm1_kernel, cudaFuncAttributeMaxDynamicSharedMemorySize, G_SMEM);
    cudaFuncSetAttribute(gemm2_kernel, cudaFuncAttributeMaxDynamicSharedMemorySize, G_SMEM);

    convert_kernel<<<1024, 256>>>(x,  0, (T_TOK*HD)/4);
    convert_kernel<<<4096, 256>>>(wg, 1, (int)(((size_t)NE*HD*ID)/4));
    convert_kernel<<<4096, 256>>>(wu, 2, (int)(((size_t)NE*HD*ID)/4));
    convert_kernel<<<4096, 256>>>(wd, 3, (int)(((size_t)NE*ID*HD)/4));

    gate_kernel<<<T_TOK/32, 256>>>(x, gate_w);
    topk_kernel<<<T_TOK, 64>>>();
    route_kernel<<<NE, 256>>>();

    gemm1_kernel<<<dim3(ID/64,  CAPE/128, NE), 256, G_SMEM>>>();
    gemm2_kernel<<<dim3(HD/128, CAPE/128, NE), 256, G_SMEM>>>();
    combine_kernel<<<T_TOK, 256>>>(y);
}